// round 2
// baseline (speedup 1.0000x reference)
#include <cuda_runtime.h>
#include <math.h>

// Problem constants
#define BB   2048
#define KK   64
#define MM   64
#define DD   256
#define NITR 15
#define MITR 3
#define INV_EPS 20.0f    // 1/0.05

// Output layout: [sigmoid(-c) (B)] [T (B*K*M)] [C (B*K*M)] [c (B)]
#define OUT_T  ((size_t)BB)
#define OUT_C  ((size_t)BB + (size_t)BB*KK*MM)
#define OUT_CV ((size_t)BB + 2*(size_t)BB*KK*MM)

// Scratch for MLP outputs (allocation-free per harness rules)
__device__ float g_Fq[(size_t)BB * KK * DD];   // 134 MB
__device__ float g_Fr[(size_t)BB * MM * DD];   // 134 MB

__device__ __forceinline__ float wredsum(float v) {
#pragma unroll
    for (int o = 16; o > 0; o >>= 1) v += __shfl_xor_sync(0xffffffffu, v, o);
    return v;
}
__device__ __forceinline__ float wredmax(float v) {
#pragma unroll
    for (int o = 16; o > 0; o >>= 1) v = fmaxf(v, __shfl_xor_sync(0xffffffffu, v, o));
    return v;
}

// ---------------------------------------------------------------------------
// Kernel 1: fused 2-layer MLP.  Each CTA: 64 rows x 256 cols, both layers.
// H tile stays in SMEM (never hits DRAM). W1/W2 streamed from L2.
// Thread (rg = t/16, cg = t%16) owns rows {rg+16i}, cols {cg+16j}: 4x16 microtile.
// ---------------------------------------------------------------------------
#define SMEM1_FLOATS (32*65 + 32*256 + 64*261)

__global__ __launch_bounds__(256, 2)
void mlp2_kernel(const float* __restrict__ X,
                 const float* __restrict__ W1, const float* __restrict__ b1,
                 const float* __restrict__ W2, const float* __restrict__ b2,
                 int which)
{
    extern __shared__ float sm[];
    float* Xs = sm;                    // [32][65]  (k-major, padded)
    float* Ws = sm + 32*65;            // [32][256] (k-major)
    float* Hs = sm + 32*65 + 32*256;   // [64][261] (row-major, padded)

    const int t  = threadIdx.x;
    const int rg = t >> 4;             // 0..15
    const int cg = t & 15;             // 0..15
    const int lr = t >> 2;             // 0..63  (load row)
    const int lo = (t & 3) << 3;       // 0,8,16,24 (load col offset)
    const size_t row0 = (size_t)blockIdx.x * 64;

    float acc[4][16];
#pragma unroll
    for (int i = 0; i < 4; i++)
#pragma unroll
        for (int j = 0; j < 16; j++) acc[i][j] = 0.f;

    // ---- GEMM1: H = relu(X @ W1^T + b1) ----
    for (int kc = 0; kc < DD; kc += 32) {
        float4 x0 = *(const float4*)(X + (row0 + lr)*DD + kc + lo);
        float4 x1 = *(const float4*)(X + (row0 + lr)*DD + kc + lo + 4);
        float4 wv[8];
#pragma unroll
        for (int j4 = 0; j4 < 8; j4++)
            wv[j4] = *(const float4*)(W1 + (size_t)t*DD + kc + j4*4);
        __syncthreads();
        Xs[(lo+0)*65+lr]=x0.x; Xs[(lo+1)*65+lr]=x0.y; Xs[(lo+2)*65+lr]=x0.z; Xs[(lo+3)*65+lr]=x0.w;
        Xs[(lo+4)*65+lr]=x1.x; Xs[(lo+5)*65+lr]=x1.y; Xs[(lo+6)*65+lr]=x1.z; Xs[(lo+7)*65+lr]=x1.w;
#pragma unroll
        for (int j4 = 0; j4 < 8; j4++) {
            Ws[(j4*4+0)*256+t]=wv[j4].x; Ws[(j4*4+1)*256+t]=wv[j4].y;
            Ws[(j4*4+2)*256+t]=wv[j4].z; Ws[(j4*4+3)*256+t]=wv[j4].w;
        }
        __syncthreads();
#pragma unroll
        for (int dk = 0; dk < 32; dk++) {
            float a[4], bv[16];
#pragma unroll
            for (int i = 0; i < 4; i++) a[i] = Xs[dk*65 + rg + 16*i];
#pragma unroll
            for (int j = 0; j < 16; j++) bv[j] = Ws[dk*256 + cg + 16*j];
#pragma unroll
            for (int i = 0; i < 4; i++)
#pragma unroll
                for (int j = 0; j < 16; j++) acc[i][j] = fmaf(a[i], bv[j], acc[i][j]);
        }
    }
    // bias + relu -> Hs, reset acc
#pragma unroll
    for (int j = 0; j < 16; j++) {
        float bj = b1[cg + 16*j];
#pragma unroll
        for (int i = 0; i < 4; i++) {
            Hs[(rg+16*i)*261 + cg + 16*j] = fmaxf(acc[i][j] + bj, 0.f);
            acc[i][j] = 0.f;
        }
    }

    // ---- GEMM2: F = H @ W2^T + b2 ----
    for (int kc = 0; kc < DD; kc += 32) {
        float4 wv[8];
#pragma unroll
        for (int j4 = 0; j4 < 8; j4++)
            wv[j4] = *(const float4*)(W2 + (size_t)t*DD + kc + j4*4);
        __syncthreads();
#pragma unroll
        for (int j4 = 0; j4 < 8; j4++) {
            Ws[(j4*4+0)*256+t]=wv[j4].x; Ws[(j4*4+1)*256+t]=wv[j4].y;
            Ws[(j4*4+2)*256+t]=wv[j4].z; Ws[(j4*4+3)*256+t]=wv[j4].w;
        }
        __syncthreads();
#pragma unroll
        for (int dk = 0; dk < 32; dk++) {
            float a[4], bv[16];
#pragma unroll
            for (int i = 0; i < 4; i++) a[i] = Hs[(rg+16*i)*261 + kc + dk];
#pragma unroll
            for (int j = 0; j < 16; j++) bv[j] = Ws[dk*256 + cg + 16*j];
#pragma unroll
            for (int i = 0; i < 4; i++)
#pragma unroll
                for (int j = 0; j < 16; j++) acc[i][j] = fmaf(a[i], bv[j], acc[i][j]);
        }
    }
    float* F = which ? g_Fr : g_Fq;
#pragma unroll
    for (int j = 0; j < 16; j++) {
        float bj = b2[cg + 16*j];
#pragma unroll
        for (int i = 0; i < 4; i++)
            F[(row0 + rg + 16*i)*DD + cg + 16*j] = acc[i][j] + bj;
    }
}

// ---------------------------------------------------------------------------
// Kernel 2: per-batch cdist + Sinkhorn + power iters, fully in SMEM.
// One CTA (256 thr, 8 warps) per batch.
// ---------------------------------------------------------------------------
#define SMEM2_FLOATS (64*33*2 + 64*65*3 + 8*64 + 8)

__global__ __launch_bounds__(256, 3)
void sinkhorn_kernel(const float* __restrict__ mq, const float* __restrict__ mr,
                     float* __restrict__ out)
{
    extern __shared__ float sm[];
    float* Qs   = sm;                  // [64][33]
    float* Rs   = Qs + 64*33;          // [64][33]
    float* Cs   = Rs + 64*33;          // [64][65]
    float* lKs  = Cs + 64*65;          // [64][65]
    float* Ts   = lKs + 64*65;         // [64][65]
    float* nqs  = Ts + 64*65;          // 64
    float* nrs  = nqs + 64;
    float* lmqs = nrs + 64;
    float* lmrs = lmqs + 64;
    float* las  = lmrs + 64;
    float* lbs  = las + 64;
    float* rss  = lbs + 64;
    float* css  = rss + 64;
    float* wred = css + 64;            // 8

    const int t = threadIdx.x;
    const int w = t >> 5, lane = t & 31;
    const int tr = t >> 4, tc = t & 15;
    const int lr = t >> 2, lo = (t & 3) << 3;
    const int b = blockIdx.x;

    if (t < 64) {
        nqs[t] = 0.f; nrs[t] = 0.f;
        lmqs[t] = __logf(fmaxf(mq[b*64 + t], 1e-8f));
        lmrs[t] = __logf(fmaxf(mr[b*64 + t], 1e-8f));
        las[t] = 0.f; lbs[t] = 0.f;
    }

    // ---- Gram G = fq @ fr^T (4x4 microtile per thread) + row norms ----
    float g[4][4];
#pragma unroll
    for (int i = 0; i < 4; i++)
#pragma unroll
        for (int j = 0; j < 4; j++) g[i][j] = 0.f;

    for (int kc = 0; kc < DD; kc += 32) {
        float4 q0 = *(const float4*)(g_Fq + ((size_t)b*64 + lr)*DD + kc + lo);
        float4 q1 = *(const float4*)(g_Fq + ((size_t)b*64 + lr)*DD + kc + lo + 4);
        float4 r0 = *(const float4*)(g_Fr + ((size_t)b*64 + lr)*DD + kc + lo);
        float4 r1 = *(const float4*)(g_Fr + ((size_t)b*64 + lr)*DD + kc + lo + 4);
        __syncthreads();
        Qs[lr*33+lo+0]=q0.x; Qs[lr*33+lo+1]=q0.y; Qs[lr*33+lo+2]=q0.z; Qs[lr*33+lo+3]=q0.w;
        Qs[lr*33+lo+4]=q1.x; Qs[lr*33+lo+5]=q1.y; Qs[lr*33+lo+6]=q1.z; Qs[lr*33+lo+7]=q1.w;
        Rs[lr*33+lo+0]=r0.x; Rs[lr*33+lo+1]=r0.y; Rs[lr*33+lo+2]=r0.z; Rs[lr*33+lo+3]=r0.w;
        Rs[lr*33+lo+4]=r1.x; Rs[lr*33+lo+5]=r1.y; Rs[lr*33+lo+6]=r1.z; Rs[lr*33+lo+7]=r1.w;
        __syncthreads();
        // partial row norms (warp w owns rows w*8..w*8+7; lane = k within chunk)
#pragma unroll
        for (int s = 0; s < 8; s++) {
            int r = w*8 + s;
            float vq = Qs[r*33 + lane]; vq *= vq;
            float vr = Rs[r*33 + lane]; vr *= vr;
            vq = wredsum(vq); vr = wredsum(vr);
            if (lane == 0) { nqs[r] += vq; nrs[r] += vr; }
        }
#pragma unroll
        for (int dk = 0; dk < 32; dk++) {
            float a[4], bv[4];
#pragma unroll
            for (int i = 0; i < 4; i++) a[i]  = Qs[(16*i + tr)*33 + dk];
#pragma unroll
            for (int j = 0; j < 4; j++) bv[j] = Rs[(16*j + tc)*33 + dk];
#pragma unroll
            for (int i = 0; i < 4; i++)
#pragma unroll
                for (int j = 0; j < 4; j++) g[i][j] = fmaf(a[i], bv[j], g[i][j]);
        }
    }
    __syncthreads();

    // ---- C = sqrt(clip(nq + nr - 2G, 0)); lK = -C/eps + log mq + log mr ----
#pragma unroll
    for (int i = 0; i < 4; i++) {
        int k = 16*i + tr;
#pragma unroll
        for (int j = 0; j < 4; j++) {
            int m = 16*j + tc;
            float v  = nqs[k] + nrs[m] - 2.f*g[i][j];
            float Cv = sqrtf(fmaxf(v, 0.f));
            Cs[k*65 + m]  = Cv;
            lKs[k*65 + m] = fmaf(-INV_EPS, Cv, lmqs[k] + lmrs[m]);
        }
    }
    __syncthreads();

    // ---- Sinkhorn: 15 iterations of row/col logsumexp ----
    for (int it = 0; it < NITR; it++) {
#pragma unroll 1
        for (int s = 0; s < 8; s++) {           // la: rows
            int r = w*8 + s;
            float v0 = lKs[r*65 + lane]      + lbs[lane];
            float v1 = lKs[r*65 + 32 + lane] + lbs[32 + lane];
            float mx = wredmax(fmaxf(v0, v1));
            float ss = wredsum(__expf(v0 - mx) + __expf(v1 - mx));
            if (lane == 0) las[r] = -(mx + __logf(ss));
        }
        __syncthreads();
#pragma unroll 1
        for (int s = 0; s < 8; s++) {           // lb: cols (pad 65 -> conflict-free)
            int cI = w*8 + s;
            float v0 = lKs[lane*65 + cI]      + las[lane];
            float v1 = lKs[(lane+32)*65 + cI] + las[lane+32];
            float mx = wredmax(fmaxf(v0, v1));
            float ss = wredsum(__expf(v0 - mx) + __expf(v1 - mx));
            if (lane == 0) lbs[cI] = -(mx + __logf(ss));
        }
        __syncthreads();
    }

    // ---- T = exp(lK + la + lb) ----
    for (int idx = t; idx < 4096; idx += 256) {
        int k = idx >> 6, m = idx & 63;
        Ts[k*65 + m] = __expf(lKs[k*65 + m] + las[k] + lbs[m]);
    }
    __syncthreads();

    // ---- 3 power iterations: square, row-normalize, col-normalize ----
    for (int p = 0; p < MITR; p++) {
#pragma unroll 1
        for (int s = 0; s < 8; s++) {           // square + row sums
            int r = w*8 + s;
            float v0 = Ts[r*65 + lane];      v0 *= v0;
            float v1 = Ts[r*65 + 32 + lane]; v1 *= v1;
            Ts[r*65 + lane] = v0; Ts[r*65 + 32 + lane] = v1;
            float ssum = wredsum(v0 + v1);
            if (lane == 0) rss[r] = ssum + 1e-8f;
        }
        __syncthreads();
#pragma unroll 1
        for (int s = 0; s < 8; s++) {           // row divide + col sums
            int cI = w*8 + s;
            float v0 = Ts[lane*65 + cI]      / rss[lane];
            float v1 = Ts[(lane+32)*65 + cI] / rss[lane+32];
            Ts[lane*65 + cI] = v0; Ts[(lane+32)*65 + cI] = v1;
            float ssum = wredsum(v0 + v1);
            if (lane == 0) css[cI] = ssum + 1e-8f;
        }
        __syncthreads();
        for (int idx = t; idx < 4096; idx += 256) {   // col divide
            int k = idx >> 6, m = idx & 63;
            Ts[k*65 + m] /= css[m];
        }
        __syncthreads();
    }

    // ---- outputs: T, C, c = sum(T*C), sigmoid(-c) ----
    size_t tbase = OUT_T + (size_t)b*4096;
    size_t cbase = OUT_C + (size_t)b*4096;
    float part = 0.f;
    for (int idx = t; idx < 4096; idx += 256) {
        int k = idx >> 6, m = idx & 63;
        float tv = Ts[k*65 + m];
        float cv = Cs[k*65 + m];
        out[tbase + idx] = tv;
        out[cbase + idx] = cv;
        part += tv * cv;
    }
    part = wredsum(part);
    if (lane == 0) wred[w] = part;
    __syncthreads();
    if (t == 0) {
        float cv = 0.f;
#pragma unroll
        for (int i = 0; i < 8; i++) cv += wred[i];
        out[b] = 1.f / (1.f + expf(cv));
        out[OUT_CV + b] = cv;
    }
}

// ---------------------------------------------------------------------------
extern "C" void kernel_launch(void* const* d_in, const int* in_sizes, int n_in,
                              void* d_out, int out_size)
{
    const float* sq = (const float*)d_in[0];
    const float* sr = (const float*)d_in[1];
    const float* mq = (const float*)d_in[2];
    const float* mr = (const float*)d_in[3];
    const float* W1 = (const float*)d_in[4];
    const float* b1 = (const float*)d_in[5];
    const float* W2 = (const float*)d_in[6];
    const float* b2 = (const float*)d_in[7];
    float* out = (float*)d_out;

    const int smem1 = SMEM1_FLOATS * 4;   // 107904 B
    const int smem2 = SMEM2_FLOATS * 4;   //  68896 B
    cudaFuncSetAttribute(mlp2_kernel,     cudaFuncAttributeMaxDynamicSharedMemorySize, smem1);
    cudaFuncSetAttribute(sinkhorn_kernel, cudaFuncAttributeMaxDynamicSharedMemorySize, smem2);

    mlp2_kernel<<<(BB*KK)/64, 256, smem1>>>(sq, W1, b1, W2, b2, 0);
    mlp2_kernel<<<(BB*MM)/64, 256, smem1>>>(sr, W1, b1, W2, b2, 1);
    sinkhorn_kernel<<<BB, 256, smem2>>>(mq, mr, out);
}

// round 15
// speedup vs baseline: 2.2466x; 2.2466x over previous
#include <cuda_runtime.h>
#include <cstdint>
#include <math.h>

// ---------------------------------------------------------------- constants
#define BB   2048
#define DD   256
#define NITR 15
#define MITR 3
#define INV_EPS 20.0f

#define OUT_T  ((size_t)BB)
#define OUT_C  ((size_t)BB + (size_t)BB*64*64)
#define OUT_CV ((size_t)BB + 2*(size_t)BB*64*64)

#define HALF_ROWS 131072                      // BB*64
#define HALF_OFF  ((size_t)HALF_ROWS * DD)    // 33554432 floats

// scratch (allocation-free): H = layer1 output, F = layer2 output (fq|fr halves)
__device__ float g_H[2u * HALF_ROWS * DD];
__device__ float g_F[2u * HALF_ROWS * DD];

// tcgen05 is an arch-SPECIFIC (sm_103a) feature; the harness build includes a
// plain compute_103 pass, so tcgen05 must be guarded with an FFMA fallback.
#if defined(__CUDA_ARCH_FEAT_SM103_ALL)
#define HAS_TCGEN05 1
#else
#define HAS_TCGEN05 0
#endif

// ---------------------------------------------------------------- ptx helpers
#if HAS_TCGEN05
__device__ __forceinline__ uint32_t smem_u32(const void* p) {
    uint32_t a;
    asm("{ .reg .u64 t; cvta.to.shared.u64 t, %1; cvt.u32.u64 %0, t; }" : "=r"(a) : "l"(p));
    return a;
}
__device__ __forceinline__ uint32_t elect_one_pred() {
    uint32_t p;
    asm volatile("{\n\t.reg .pred p;\n\telect.sync _|p, 0xFFFFFFFF;\n\tselp.b32 %0, 1, 0, p;\n\t}" : "=r"(p));
    return p;
}
#define TCGEN05_ALLOC(sa, n) \
    asm volatile("tcgen05.alloc.cta_group::1.sync.aligned.shared::cta.b32 [%0], %1;" :: "r"((uint32_t)(sa)), "r"((uint32_t)(n)) : "memory")
#define TCGEN05_DEALLOC(ta, n) \
    asm volatile("tcgen05.dealloc.cta_group::1.sync.aligned.b32 %0, %1;" :: "r"(ta), "r"((uint32_t)(n)))
#define TCGEN05_RELINQ() \
    asm volatile("tcgen05.relinquish_alloc_permit.cta_group::1.sync.aligned;")
#define TCGEN05_COMMIT(mb) \
    asm volatile("tcgen05.commit.cta_group::1.mbarrier::arrive::one.shared::cluster.b64 [%0];" :: "r"((uint32_t)(mb)) : "memory")
#define MBARRIER_INIT(mb, cnt) \
    asm volatile("mbarrier.init.shared.b64 [%0], %1;" :: "r"((uint32_t)(mb)), "r"((uint32_t)(cnt)) : "memory")
#define MBARRIER_WAIT_PARITY(mb, par) do { \
    uint32_t _mb = (uint32_t)(mb); uint32_t _p = (uint32_t)(par); uint32_t _done; \
    asm volatile("{\n\t.reg .pred p;\n\tmbarrier.try_wait.parity.acquire.cta.shared::cta.b64 p, [%1], %2;\n\tselp.b32 %0, 1, 0, p;\n\t}" \
        : "=r"(_done) : "r"(_mb), "r"(_p) : "memory"); \
    if (!_done) { \
        asm volatile("{\n\t.reg .pred P1;\n\tWL_%=:\n\tmbarrier.try_wait.parity.acquire.cta.shared::cta.b64 P1, [%0], %1, 0x989680;\n\t@P1 bra.uni WD_%=;\n\tbra.uni WL_%=;\n\tWD_%=:\n\t}" \
            :: "r"(_mb), "r"(_p) : "memory"); \
    } } while (0)
#define TCGEN05_FENCE_AFTER()  asm volatile("tcgen05.fence::after_thread_sync;" ::: "memory")
#define TCGEN05_FENCE_BEFORE() asm volatile("tcgen05.fence::before_thread_sync;" ::: "memory")
#define FENCE_ASYNC_SHARED()   asm volatile("fence.proxy.async.shared::cta;" ::: "memory")
#define TCGEN05_WAIT_LD()      asm volatile("tcgen05.wait::ld.sync.aligned;" ::: "memory")

#define TCGEN05_LD_32X32B_X32(r, ta) \
    asm volatile("tcgen05.ld.sync.aligned.32x32b.x32.b32 " \
        "{%0, %1, %2, %3, %4, %5, %6, %7, %8, %9, %10, %11, %12, %13, %14, %15, " \
        " %16, %17, %18, %19, %20, %21, %22, %23, %24, %25, %26, %27, %28, %29, %30, %31}, [%32];" \
        : "=r"((r)[0]),  "=r"((r)[1]),  "=r"((r)[2]),  "=r"((r)[3]), \
          "=r"((r)[4]),  "=r"((r)[5]),  "=r"((r)[6]),  "=r"((r)[7]), \
          "=r"((r)[8]),  "=r"((r)[9]),  "=r"((r)[10]), "=r"((r)[11]), \
          "=r"((r)[12]), "=r"((r)[13]), "=r"((r)[14]), "=r"((r)[15]), \
          "=r"((r)[16]), "=r"((r)[17]), "=r"((r)[18]), "=r"((r)[19]), \
          "=r"((r)[20]), "=r"((r)[21]), "=r"((r)[22]), "=r"((r)[23]), \
          "=r"((r)[24]), "=r"((r)[25]), "=r"((r)[26]), "=r"((r)[27]), \
          "=r"((r)[28]), "=r"((r)[29]), "=r"((r)[30]), "=r"((r)[31]) \
        : "r"(ta))

// SW128 K-major descriptor (verified constants from examples)
static constexpr uint64_t SMEM_DESC_BASE_SW128 =
    (uint64_t(2) << 61) | (uint64_t(1) << 46) | (uint64_t(64) << 32) | (uint64_t(1) << 16);
#define MAKE_SMEM_DESC(ba) (SMEM_DESC_BASE_SW128 | ((uint64_t)((ba) >> 4) & 0x3FFF))

// tf32 SS MMA, cta_group::1.  idesc: F32 dtype, TF32 a/b, N=256, M=128
static constexpr uint32_t IDESC_TF32 =
    (1u << 4) | (2u << 7) | (2u << 10) | ((256u / 8) << 17) | ((128u / 16) << 24);

__device__ __forceinline__ void mma_tf32_ss(uint32_t d, uint64_t a, uint64_t b, uint32_t en) {
    asm volatile(
        "{\n\t.reg .pred p;\n\tsetp.ne.u32 p, %5, 0;\n\t"
        "tcgen05.mma.cta_group::1.kind::tf32 [%0], %1, %2, %3, {%4, %4, %4, %4}, p;\n\t}"
        :: "r"(d), "l"(a), "l"(b), "r"(IDESC_TF32), "r"(0u), "r"(en) : "memory");
}
#endif  // HAS_TCGEN05

__device__ __forceinline__ float tfhi(float x) {
    return __uint_as_float(__float_as_uint(x) & 0xffffe000u);
}

__device__ __forceinline__ float wredsum(float v) {
#pragma unroll
    for (int o = 16; o > 0; o >>= 1) v += __shfl_xor_sync(0xffffffffu, v, o);
    return v;
}

// ---------------------------------------------------------------------------
// MLP layer: Y[128 x 256] = act(X[128 x 256] @ W^T + b)
// sm_103a: tcgen05 tf32 Dekker 3-pass. otherwise: FFMA fallback.
// ---------------------------------------------------------------------------
#define STAGE_BYTES 98304u         // Ahi 16K | Alo 16K | Bhi 32K | Blo 32K
#define SMEM_MMA    (1024u + 2u*STAGE_BYTES)

#if HAS_TCGEN05
__device__ __forceinline__ void load_split_chunk(
    const float* __restrict__ X, const float* __restrict__ W,
    size_t xrow0, int kc, char* smem, uint32_t sb)
{
    const int t = threadIdx.x;
    if (t < 128) {                                   // A: 128 rows x 32 cols
        const float* src = X + (xrow0 + (size_t)t) * DD + kc;
#pragma unroll
        for (int j4 = 0; j4 < 8; j4++) {
            float4 v = *(const float4*)(src + j4 * 4);
            float4 h, l;
            h.x = tfhi(v.x); h.y = tfhi(v.y); h.z = tfhi(v.z); h.w = tfhi(v.w);
            l.x = v.x - h.x; l.y = v.y - h.y; l.z = v.z - h.z; l.w = v.w - h.w;
            uint32_t bo = (uint32_t)t * 128u + (uint32_t)j4 * 16u;
            uint32_t sw = bo ^ ((bo >> 3) & 0x70u);
            *(float4*)(smem + sb + 0u     + sw) = h;
            *(float4*)(smem + sb + 16384u + sw) = l;
        }
    }
    {                                                // B: 256 rows (W rows) x 32 cols
        const float* src = W + (size_t)t * DD + kc;
#pragma unroll
        for (int j4 = 0; j4 < 8; j4++) {
            float4 v = *(const float4*)(src + j4 * 4);
            float4 h, l;
            h.x = tfhi(v.x); h.y = tfhi(v.y); h.z = tfhi(v.z); h.w = tfhi(v.w);
            l.x = v.x - h.x; l.y = v.y - h.y; l.z = v.z - h.z; l.w = v.w - h.w;
            uint32_t bo = (uint32_t)t * 128u + (uint32_t)j4 * 16u;
            uint32_t sw = bo ^ ((bo >> 3) & 0x70u);
            *(float4*)(smem + sb + 32768u + sw) = h;
            *(float4*)(smem + sb + 65536u + sw) = l;
        }
    }
}
#endif

__global__ __launch_bounds__(256, 1)
void mma_mlp_layer(const float* __restrict__ X0, const float* __restrict__ X1,
                   const float* __restrict__ W,  const float* __restrict__ bias,
                   int layer)
{
    extern __shared__ char smem[];
    const int t = threadIdx.x;
    const uint32_t bid = blockIdx.x;
    const uint32_t half = gridDim.x >> 1;

    const float* X;
    float* Y;
    size_t xrow0;
    const size_t yrow0 = (size_t)bid * 128;
    if (layer == 0) {
        X = (bid < half) ? X0 : X1;
        xrow0 = (size_t)(bid < half ? bid : bid - half) * 128;
        Y = g_H;
    } else {
        X = g_H; xrow0 = yrow0; Y = g_F;
    }

#if HAS_TCGEN05
    const uint32_t sbase = smem_u32(smem);
    const int wid = t >> 5, lane = t & 31;

    if (wid == 0) { TCGEN05_ALLOC(sbase + 0, 512); TCGEN05_RELINQ(); }
    if (t == 0)   { MBARRIER_INIT(sbase + 8, 1); MBARRIER_INIT(sbase + 16, 1); }

    load_split_chunk(X, W, xrow0, 0, smem, 1024u);
    FENCE_ASYNC_SHARED();
    __syncthreads();

    uint32_t tmem;
    asm volatile("ld.shared.b32 %0, [%1];" : "=r"(tmem) : "r"(sbase + 0));

    int pc0 = 0, pc1 = 0;
#pragma unroll 1
    for (int c = 0; c < 8; c++) {
        const uint32_t sb = 1024u + (uint32_t)(c & 1) * STAGE_BYTES;
        if (wid == 0 && elect_one_pred()) {
            uint64_t dAhi = MAKE_SMEM_DESC(sbase + sb + 0u);
            uint64_t dAlo = MAKE_SMEM_DESC(sbase + sb + 16384u);
            uint64_t dBhi = MAKE_SMEM_DESC(sbase + sb + 32768u);
            uint64_t dBlo = MAKE_SMEM_DESC(sbase + sb + 65536u);
#pragma unroll
            for (int ks = 0; ks < 4; ks++)
                mma_tf32_ss(tmem, dAhi + ks * 2, dBhi + ks * 2, (c == 0 && ks == 0) ? 0u : 1u);
#pragma unroll
            for (int ks = 0; ks < 4; ks++)
                mma_tf32_ss(tmem, dAhi + ks * 2, dBlo + ks * 2, 1u);
#pragma unroll
            for (int ks = 0; ks < 4; ks++)
                mma_tf32_ss(tmem, dAlo + ks * 2, dBhi + ks * 2, 1u);
            TCGEN05_COMMIT(sbase + 8 + (uint32_t)(c & 1) * 8u);
        }
        if (c < 7) {
            int s = (c + 1) & 1;
            if (c >= 1) {
                if (s == 0) { MBARRIER_WAIT_PARITY(sbase + 8,  pc0 & 1); pc0++; }
                else        { MBARRIER_WAIT_PARITY(sbase + 16, pc1 & 1); pc1++; }
            }
            load_split_chunk(X, W, xrow0, (c + 1) * 32, smem, 1024u + (uint32_t)s * STAGE_BYTES);
            FENCE_ASYNC_SHARED();
            __syncthreads();
        }
    }
    MBARRIER_WAIT_PARITY(sbase + 16, pc1 & 1); pc1++;
    TCGEN05_FENCE_AFTER();

    {
        const int rsub  = wid & 3;
        const int chalf = (wid >> 2) * 128;
        float* dst = Y + (yrow0 + (size_t)(rsub * 32 + lane)) * DD + chalf;
#pragma unroll
        for (int c0 = 0; c0 < 4; c0++) {
            uint32_t r[32];
            TCGEN05_LD_32X32B_X32(r, tmem + (uint32_t)chalf + (uint32_t)c0 * 32u);
            TCGEN05_WAIT_LD();
#pragma unroll
            for (int j = 0; j < 32; j += 4) {
                float4 v;
                v.x = __uint_as_float(r[j + 0]) + bias[chalf + c0 * 32 + j + 0];
                v.y = __uint_as_float(r[j + 1]) + bias[chalf + c0 * 32 + j + 1];
                v.z = __uint_as_float(r[j + 2]) + bias[chalf + c0 * 32 + j + 2];
                v.w = __uint_as_float(r[j + 3]) + bias[chalf + c0 * 32 + j + 3];
                if (layer == 0) {
                    v.x = fmaxf(v.x, 0.f); v.y = fmaxf(v.y, 0.f);
                    v.z = fmaxf(v.z, 0.f); v.w = fmaxf(v.w, 0.f);
                }
                *(float4*)(dst + c0 * 32 + j) = v;
            }
        }
        TCGEN05_FENCE_BEFORE();
    }
    __syncthreads();
    if (wid == 0) TCGEN05_DEALLOC(tmem, 512);

#else   // ------------------- FFMA fallback (compute_103 pass) -------------
    float* smf = (float*)smem;
    float* Xs = smf;                 // [32][65] k-major
    float* Ws = smf + 32 * 65;       // [32][256] k-major
    const int rg = t >> 4;
    const int cg = t & 15;
    const int lr = t >> 2;
    const int lo = (t & 3) << 3;

#pragma unroll 1
    for (int hrow = 0; hrow < 2; hrow++) {
        const size_t r0 = xrow0 + (size_t)hrow * 64;
        float acc[4][16];
#pragma unroll
        for (int i = 0; i < 4; i++)
#pragma unroll
            for (int j = 0; j < 16; j++) acc[i][j] = 0.f;

        for (int kc = 0; kc < DD; kc += 32) {
            float4 x0 = *(const float4*)(X + (r0 + lr) * DD + kc + lo);
            float4 x1 = *(const float4*)(X + (r0 + lr) * DD + kc + lo + 4);
            float4 wv[8];
#pragma unroll
            for (int j4 = 0; j4 < 8; j4++)
                wv[j4] = *(const float4*)(W + (size_t)t * DD + kc + j4 * 4);
            __syncthreads();
            Xs[(lo+0)*65+lr]=x0.x; Xs[(lo+1)*65+lr]=x0.y; Xs[(lo+2)*65+lr]=x0.z; Xs[(lo+3)*65+lr]=x0.w;
            Xs[(lo+4)*65+lr]=x1.x; Xs[(lo+5)*65+lr]=x1.y; Xs[(lo+6)*65+lr]=x1.z; Xs[(lo+7)*65+lr]=x1.w;
#pragma unroll
            for (int j4 = 0; j4 < 8; j4++) {
                Ws[(j4*4+0)*256+t]=wv[j4].x; Ws[(j4*4+1)*256+t]=wv[j4].y;
                Ws[(j4*4+2)*256+t]=wv[j4].z; Ws[(j4*4+3)*256+t]=wv[j4].w;
            }
            __syncthreads();
#pragma unroll
            for (int dk = 0; dk < 32; dk++) {
                float a[4], bv[16];
#pragma unroll
                for (int i = 0; i < 4; i++) a[i] = Xs[dk*65 + rg + 16*i];
#pragma unroll
                for (int j = 0; j < 16; j++) bv[j] = Ws[dk*256 + cg + 16*j];
#pragma unroll
                for (int i = 0; i < 4; i++)
#pragma unroll
                    for (int j = 0; j < 16; j++) acc[i][j] = fmaf(a[i], bv[j], acc[i][j]);
            }
        }
        __syncthreads();
#pragma unroll
        for (int j = 0; j < 16; j++) {
            float bj = bias[cg + 16*j];
#pragma unroll
            for (int i = 0; i < 4; i++) {
                float v = acc[i][j] + bj;
                if (layer == 0) v = fmaxf(v, 0.f);
                Y[(yrow0 + (size_t)hrow*64 + rg + 16*i) * DD + cg + 16*j] = v;
            }
        }
    }
#endif
}

// ---------------------------------------------------------------------------
// Kernel 2: per-batch cdist + Sinkhorn + power iters, fully in SMEM.
// Quad-parallel LSE. All stride-65 accesses are SCALAR (65%4!=0 -> float4
// on r4*65 rows is misaligned; that was the R8 fault).
// ---------------------------------------------------------------------------
#define SMEM2_FLOATS (64*33*2 + 64*65*3 + 8*64 + 8)

__global__ __launch_bounds__(256, 3)
void sinkhorn_kernel(const float* __restrict__ mq, const float* __restrict__ mr,
                     float* __restrict__ out)
{
    extern __shared__ float sm[];
    float* Qs   = sm;
    float* Rs   = Qs + 64*33;
    float* Cs   = Rs + 64*33;
    float* lKs  = Cs + 64*65;
    float* Ts   = lKs + 64*65;
    float* nqs  = Ts + 64*65;
    float* nrs  = nqs + 64;
    float* lmqs = nrs + 64;
    float* lmrs = lmqs + 64;
    float* las  = lmrs + 64;
    float* lbs  = las + 64;
    float* rss  = lbs + 64;
    float* css  = rss + 64;
    float* wred = css + 64;

    const int t = threadIdx.x;
    const int w = t >> 5, lane = t & 31;
    const int tr = t >> 4, tc = t & 15;
    const int lr = t >> 2, lo = (t & 3) << 3;
    const int r4 = t >> 2;            // 0..63 : row (or col) owned by this quad
    const int q4 = (t & 3) * 16;      // 16-element segment within the 64
    const int b = blockIdx.x;

    const float* Fq = g_F;
    const float* Fr = g_F + HALF_OFF;

    if (t < 64) {
        nqs[t] = 0.f; nrs[t] = 0.f;
        lmqs[t] = __logf(fmaxf(mq[b*64 + t], 1e-8f));
        lmrs[t] = __logf(fmaxf(mr[b*64 + t], 1e-8f));
        las[t] = 0.f; lbs[t] = 0.f;
    }

    float g[4][4];
#pragma unroll
    for (int i = 0; i < 4; i++)
#pragma unroll
        for (int j = 0; j < 4; j++) g[i][j] = 0.f;

    for (int kc = 0; kc < DD; kc += 32) {
        float4 q0 = *(const float4*)(Fq + ((size_t)b*64 + lr)*DD + kc + lo);
        float4 q1 = *(const float4*)(Fq + ((size_t)b*64 + lr)*DD + kc + lo + 4);
        float4 r0 = *(const float4*)(Fr + ((size_t)b*64 + lr)*DD + kc + lo);
        float4 r1 = *(const float4*)(Fr + ((size_t)b*64 + lr)*DD + kc + lo + 4);
        __syncthreads();
        Qs[lr*33+lo+0]=q0.x; Qs[lr*33+lo+1]=q0.y; Qs[lr*33+lo+2]=q0.z; Qs[lr*33+lo+3]=q0.w;
        Qs[lr*33+lo+4]=q1.x; Qs[lr*33+lo+5]=q1.y; Qs[lr*33+lo+6]=q1.z; Qs[lr*33+lo+7]=q1.w;
        Rs[lr*33+lo+0]=r0.x; Rs[lr*33+lo+1]=r0.y; Rs[lr*33+lo+2]=r0.z; Rs[lr*33+lo+3]=r0.w;
        Rs[lr*33+lo+4]=r1.x; Rs[lr*33+lo+5]=r1.y; Rs[lr*33+lo+6]=r1.z; Rs[lr*33+lo+7]=r1.w;
        __syncthreads();
        {
            float vq = 0.f, vr = 0.f;
            int k0 = (t & 3) * 8;
#pragma unroll
            for (int j = 0; j < 8; j++) {
                float a = Qs[r4*33 + k0 + j]; vq = fmaf(a, a, vq);
                float c = Rs[r4*33 + k0 + j]; vr = fmaf(c, c, vr);
            }
            vq += __shfl_xor_sync(0xffffffffu, vq, 1);
            vq += __shfl_xor_sync(0xffffffffu, vq, 2);
            vr += __shfl_xor_sync(0xffffffffu, vr, 1);
            vr += __shfl_xor_sync(0xffffffffu, vr, 2);
            if ((t & 3) == 0) { nqs[r4] += vq; nrs[r4] += vr; }
        }
#pragma unroll
        for (int dk = 0; dk < 32; dk++) {
            float a[4], bv[4];
#pragma unroll
            for (int i = 0; i < 4; i++) a[i]  = Qs[(16*i + tr)*33 + dk];
#pragma unroll
            for (int j = 0; j < 4; j++) bv[j] = Rs[(16*j + tc)*33 + dk];
#pragma unroll
            for (int i = 0; i < 4; i++)
#pragma unroll
                for (int j = 0; j < 4; j++) g[i][j] = fmaf(a[i], bv[j], g[i][j]);
        }
    }
    __syncthreads();

#pragma unroll
    for (int i = 0; i < 4; i++) {
        int k = 16*i + tr;
#pragma unroll
        for (int j = 0; j < 4; j++) {
            int m = 16*j + tc;
            float v  = nqs[k] + nrs[m] - 2.f*g[i][j];
            float Cv = sqrtf(fmaxf(v, 0.f));
            Cs[k*65 + m]  = Cv;
            lKs[k*65 + m] = fmaf(-INV_EPS, Cv, lmqs[k] + lmrs[m]);
        }
    }
    __syncthreads();

    for (int it = 0; it < NITR; it++) {
        // la: reduce over m (row r4) — scalar LDS (stride-65 rows)
        {
            float vb[16];
            float mx = -1e30f;
#pragma unroll
            for (int j = 0; j < 16; j++) {
                vb[j] = lKs[r4*65 + q4 + j] + lbs[q4 + j];
                mx = fmaxf(mx, vb[j]);
            }
            mx = fmaxf(mx, __shfl_xor_sync(0xffffffffu, mx, 1));
            mx = fmaxf(mx, __shfl_xor_sync(0xffffffffu, mx, 2));
            float ss = 0.f;
#pragma unroll
            for (int j = 0; j < 16; j++) ss += __expf(vb[j] - mx);
            ss += __shfl_xor_sync(0xffffffffu, ss, 1);
            ss += __shfl_xor_sync(0xffffffffu, ss, 2);
            if ((t & 3) == 0) las[r4] = -(mx + __logf(ss));
        }
        __syncthreads();
        // lb: reduce over k (column r4)
        {
            float vb[16];
            float mx = -1e30f;
#pragma unroll
            for (int j = 0; j < 16; j++) {
                vb[j] = lKs[(q4 + j)*65 + r4] + las[q4 + j];
                mx = fmaxf(mx, vb[j]);
            }
            mx = fmaxf(mx, __shfl_xor_sync(0xffffffffu, mx, 1));
            mx = fmaxf(mx, __shfl_xor_sync(0xffffffffu, mx, 2));
            float ss = 0.f;
#pragma unroll
            for (int j = 0; j < 16; j++) ss += __expf(vb[j] - mx);
            ss += __shfl_xor_sync(0xffffffffu, ss, 1);
            ss += __shfl_xor_sync(0xffffffffu, ss, 2);
            if ((t & 3) == 0) lbs[r4] = -(mx + __logf(ss));
        }
        __syncthreads();
    }

    for (int idx = t; idx < 4096; idx += 256) {
        int k = idx >> 6, m = idx & 63;
        Ts[k*65 + m] = __expf(lKs[k*65 + m] + las[k] + lbs[m]);
    }
    __syncthreads();

    for (int p = 0; p < MITR; p++) {
        // square + row sums (row r4) — scalar
        {
            float ssum = 0.f;
#pragma unroll
            for (int j = 0; j < 16; j++) {
                float v = Ts[r4*65 + q4 + j];
                v *= v;
                Ts[r4*65 + q4 + j] = v;
                ssum += v;
            }
            ssum += __shfl_xor_sync(0xffffffffu, ssum, 1);
            ssum += __shfl_xor_sync(0xffffffffu, ssum, 2);
            if ((t & 3) == 0) rss[r4] = ssum + 1e-8f;
        }
        __syncthreads();
        // row divide + col sums (column r4)
        {
            float ssum = 0.f;
#pragma unroll
            for (int j = 0; j < 16; j++) {
                float v = Ts[(q4 + j)*65 + r4] / rss[q4 + j];
                Ts[(q4 + j)*65 + r4] = v;
                ssum += v;
            }
            ssum += __shfl_xor_sync(0xffffffffu, ssum, 1);
            ssum += __shfl_xor_sync(0xffffffffu, ssum, 2);
            if ((t & 3) == 0) css[r4] = ssum + 1e-8f;
        }
        __syncthreads();
        // col divide (row r4) — scalar
        {
#pragma unroll
            for (int j = 0; j < 16; j++)
                Ts[r4*65 + q4 + j] /= css[q4 + j];
        }
        __syncthreads();
    }

    size_t tbase = OUT_T + (size_t)b*4096;
    size_t cbase = OUT_C + (size_t)b*4096;
    float part = 0.f;
    for (int idx = t; idx < 4096; idx += 256) {
        int k = idx >> 6, m = idx & 63;
        float tv = Ts[k*65 + m];
        float cv = Cs[k*65 + m];
        out[tbase + idx] = tv;
        out[cbase + idx] = cv;
        part += tv * cv;
    }
    part = wredsum(part);
    if (lane == 0) wred[w] = part;
    __syncthreads();
    if (t == 0) {
        float cv = 0.f;
#pragma unroll
        for (int i = 0; i < 8; i++) cv += wred[i];
        out[b] = 1.f / (1.f + expf(cv));
        out[OUT_CV + b] = cv;
    }
}

// ---------------------------------------------------------------------------
extern "C" void kernel_launch(void* const* d_in, const int* in_sizes, int n_in,
                              void* d_out, int out_size)
{
    const float* sq = (const float*)d_in[0];
    const float* sr = (const float*)d_in[1];
    const float* mq = (const float*)d_in[2];
    const float* mr = (const float*)d_in[3];
    const float* W1 = (const float*)d_in[4];
    const float* b1 = (const float*)d_in[5];
    const float* W2 = (const float*)d_in[6];
    const float* b2 = (const float*)d_in[7];
    float* out = (float*)d_out;

    const int smem2 = SMEM2_FLOATS * 4;
    cudaFuncSetAttribute(mma_mlp_layer,   cudaFuncAttributeMaxDynamicSharedMemorySize, SMEM_MMA);
    cudaFuncSetAttribute(sinkhorn_kernel, cudaFuncAttributeMaxDynamicSharedMemorySize, smem2);

    mma_mlp_layer<<<2048, 256, SMEM_MMA>>>(sq, sr, W1, b1, 0);
    mma_mlp_layer<<<2048, 256, SMEM_MMA>>>(sq, sr, W2, b2, 1);
    sinkhorn_kernel<<<BB, 256, smem2>>>(mq, mr, out);
}

// round 17
// speedup vs baseline: 2.3439x; 1.0433x over previous
#include <cuda_runtime.h>
#include <cstdint>
#include <math.h>

// ---------------------------------------------------------------- constants
#define BB   2048
#define DD   256
#define NITR 15
#define MITR 3
#define INV_EPS 20.0f

#define OUT_T  ((size_t)BB)
#define OUT_C  ((size_t)BB + (size_t)BB*64*64)
#define OUT_CV ((size_t)BB + 2*(size_t)BB*64*64)

#define HALF_ROWS 131072                      // BB*64
#define HALF_OFF  ((size_t)HALF_ROWS * DD)    // 33554432 floats

// scratch (allocation-free): H = layer1 output, F = layer2 output (fq|fr halves)
__device__ float g_H[2u * HALF_ROWS * DD];
__device__ float g_F[2u * HALF_ROWS * DD];

// tcgen05 is an arch-SPECIFIC (sm_103a) feature; the harness build includes a
// plain compute_103 pass, so tcgen05 must be guarded with an FFMA fallback.
#if defined(__CUDA_ARCH_FEAT_SM103_ALL)
#define HAS_TCGEN05 1
#else
#define HAS_TCGEN05 0
#endif

// ---------------------------------------------------------------- ptx helpers
#if HAS_TCGEN05
__device__ __forceinline__ uint32_t smem_u32(const void* p) {
    uint32_t a;
    asm("{ .reg .u64 t; cvta.to.shared.u64 t, %1; cvt.u32.u64 %0, t; }" : "=r"(a) : "l"(p));
    return a;
}
__device__ __forceinline__ uint32_t elect_one_pred() {
    uint32_t p;
    asm volatile("{\n\t.reg .pred p;\n\telect.sync _|p, 0xFFFFFFFF;\n\tselp.b32 %0, 1, 0, p;\n\t}" : "=r"(p));
    return p;
}
#define TCGEN05_ALLOC(sa, n) \
    asm volatile("tcgen05.alloc.cta_group::1.sync.aligned.shared::cta.b32 [%0], %1;" :: "r"((uint32_t)(sa)), "r"((uint32_t)(n)) : "memory")
#define TCGEN05_DEALLOC(ta, n) \
    asm volatile("tcgen05.dealloc.cta_group::1.sync.aligned.b32 %0, %1;" :: "r"(ta), "r"((uint32_t)(n)))
#define TCGEN05_RELINQ() \
    asm volatile("tcgen05.relinquish_alloc_permit.cta_group::1.sync.aligned;")
#define TCGEN05_COMMIT(mb) \
    asm volatile("tcgen05.commit.cta_group::1.mbarrier::arrive::one.shared::cluster.b64 [%0];" :: "r"((uint32_t)(mb)) : "memory")
#define MBARRIER_INIT(mb, cnt) \
    asm volatile("mbarrier.init.shared.b64 [%0], %1;" :: "r"((uint32_t)(mb)), "r"((uint32_t)(cnt)) : "memory")
#define MBARRIER_WAIT_PARITY(mb, par) do { \
    uint32_t _mb = (uint32_t)(mb); uint32_t _p = (uint32_t)(par); uint32_t _done; \
    asm volatile("{\n\t.reg .pred p;\n\tmbarrier.try_wait.parity.acquire.cta.shared::cta.b64 p, [%1], %2;\n\tselp.b32 %0, 1, 0, p;\n\t}" \
        : "=r"(_done) : "r"(_mb), "r"(_p) : "memory"); \
    if (!_done) { \
        asm volatile("{\n\t.reg .pred P1;\n\tWL_%=:\n\tmbarrier.try_wait.parity.acquire.cta.shared::cta.b64 P1, [%0], %1, 0x989680;\n\t@P1 bra.uni WD_%=;\n\tbra.uni WL_%=;\n\tWD_%=:\n\t}" \
            :: "r"(_mb), "r"(_p) : "memory"); \
    } } while (0)
#define TCGEN05_FENCE_AFTER()  asm volatile("tcgen05.fence::after_thread_sync;" ::: "memory")
#define TCGEN05_FENCE_BEFORE() asm volatile("tcgen05.fence::before_thread_sync;" ::: "memory")
#define FENCE_ASYNC_SHARED()   asm volatile("fence.proxy.async.shared::cta;" ::: "memory")
#define TCGEN05_WAIT_LD()      asm volatile("tcgen05.wait::ld.sync.aligned;" ::: "memory")

#define TCGEN05_LD_32X32B_X32(r, ta) \
    asm volatile("tcgen05.ld.sync.aligned.32x32b.x32.b32 " \
        "{%0, %1, %2, %3, %4, %5, %6, %7, %8, %9, %10, %11, %12, %13, %14, %15, " \
        " %16, %17, %18, %19, %20, %21, %22, %23, %24, %25, %26, %27, %28, %29, %30, %31}, [%32];" \
        : "=r"((r)[0]),  "=r"((r)[1]),  "=r"((r)[2]),  "=r"((r)[3]), \
          "=r"((r)[4]),  "=r"((r)[5]),  "=r"((r)[6]),  "=r"((r)[7]), \
          "=r"((r)[8]),  "=r"((r)[9]),  "=r"((r)[10]), "=r"((r)[11]), \
          "=r"((r)[12]), "=r"((r)[13]), "=r"((r)[14]), "=r"((r)[15]), \
          "=r"((r)[16]), "=r"((r)[17]), "=r"((r)[18]), "=r"((r)[19]), \
          "=r"((r)[20]), "=r"((r)[21]), "=r"((r)[22]), "=r"((r)[23]), \
          "=r"((r)[24]), "=r"((r)[25]), "=r"((r)[26]), "=r"((r)[27]), \
          "=r"((r)[28]), "=r"((r)[29]), "=r"((r)[30]), "=r"((r)[31]) \
        : "r"(ta))

// SW64 K-major descriptor: layout=4, SBO=32 (512B = 8 rows x 64B), LBO=1 (16B)
static constexpr uint64_t SMEM_DESC_BASE_SW64 =
    (uint64_t(4) << 61) | (uint64_t(1) << 46) | (uint64_t(32) << 32) | (uint64_t(1) << 16);
#define MAKE_SMEM_DESC64(ba) (SMEM_DESC_BASE_SW64 | ((uint64_t)((ba) >> 4) & 0x3FFF))

// tf32 SS MMA, cta_group::1.  idesc: F32 dtype, TF32 a/b, N=256, M=128
// (verified by the R15 passing run)
static constexpr uint32_t IDESC_TF32 =
    (1u << 4) | (2u << 7) | (2u << 10) | ((256u / 8) << 17) | ((128u / 16) << 24);

__device__ __forceinline__ void mma_tf32_ss(uint32_t d, uint64_t a, uint64_t b, uint32_t en) {
    asm volatile(
        "{\n\t.reg .pred p;\n\tsetp.ne.u32 p, %5, 0;\n\t"
        "tcgen05.mma.cta_group::1.kind::tf32 [%0], %1, %2, %3, {%4, %4, %4, %4}, p;\n\t}"
        :: "r"(d), "l"(a), "l"(b), "r"(IDESC_TF32), "r"(0u), "r"(en) : "memory");
}
#endif  // HAS_TCGEN05

__device__ __forceinline__ float tfhi(float x) {
    return __uint_as_float(__float_as_uint(x) & 0xffffe000u);
}

__device__ __forceinline__ float wredsum(float v) {
#pragma unroll
    for (int o = 16; o > 0; o >>= 1) v += __shfl_xor_sync(0xffffffffu, v, o);
    return v;
}

// ---------------------------------------------------------------------------
// MLP layer: Y[128 x 256] = act(X[128 x 256] @ W^T + b)
// sm_103a: tcgen05 tf32 Dekker 3-pass, K=16 chunks, SW64, 2 CTAs/SM.
// otherwise: FFMA fallback.
// ---------------------------------------------------------------------------
// Stage (K=16): Ahi 8K | Alo 8K | Bhi 16K | Blo 16K = 48KB
#define STAGE_BYTES 49152u
#define SMEM_MMA    (1024u + 2u*STAGE_BYTES)   // 99328 B -> 2 CTAs/SM
#define NCHUNK      16
#define TMEM_COLS   256u

#if HAS_TCGEN05
__device__ __forceinline__ void load_split_chunk16(
    const float* __restrict__ X, const float* __restrict__ W,
    size_t xrow0, int kc, char* smem, uint32_t sb)
{
    const int t = threadIdx.x;
    if (t < 128) {                                   // A: 128 rows x 16 cols (64B rows)
        const float* src = X + (xrow0 + (size_t)t) * DD + kc;
#pragma unroll
        for (int j4 = 0; j4 < 4; j4++) {
            float4 v = *(const float4*)(src + j4 * 4);
            float4 h, l;
            h.x = tfhi(v.x); h.y = tfhi(v.y); h.z = tfhi(v.z); h.w = tfhi(v.w);
            l.x = v.x - h.x; l.y = v.y - h.y; l.z = v.z - h.z; l.w = v.w - h.w;
            uint32_t bo = (uint32_t)t * 64u + (uint32_t)j4 * 16u;
            uint32_t sw = bo ^ ((bo >> 3) & 0x30u);           // SW64 swizzle
            *(float4*)(smem + sb + 0u    + sw) = h;
            *(float4*)(smem + sb + 8192u + sw) = l;
        }
    }
    {                                                // B: 256 rows (W rows) x 16 cols
        const float* src = W + (size_t)t * DD + kc;
#pragma unroll
        for (int j4 = 0; j4 < 4; j4++) {
            float4 v = *(const float4*)(src + j4 * 4);
            float4 h, l;
            h.x = tfhi(v.x); h.y = tfhi(v.y); h.z = tfhi(v.z); h.w = tfhi(v.w);
            l.x = v.x - h.x; l.y = v.y - h.y; l.z = v.z - h.z; l.w = v.w - h.w;
            uint32_t bo = (uint32_t)t * 64u + (uint32_t)j4 * 16u;
            uint32_t sw = bo ^ ((bo >> 3) & 0x30u);
            *(float4*)(smem + sb + 16384u + sw) = h;
            *(float4*)(smem + sb + 32768u + sw) = l;
        }
    }
}
#endif

__global__ __launch_bounds__(256, 2)
void mma_mlp_layer(const float* __restrict__ X0, const float* __restrict__ X1,
                   const float* __restrict__ W,  const float* __restrict__ bias,
                   int layer)
{
    extern __shared__ char smem[];
    const int t = threadIdx.x;
    const uint32_t bid = blockIdx.x;
    const uint32_t half = gridDim.x >> 1;

    const float* X;
    float* Y;
    size_t xrow0;
    const size_t yrow0 = (size_t)bid * 128;
    if (layer == 0) {
        X = (bid < half) ? X0 : X1;
        xrow0 = (size_t)(bid < half ? bid : bid - half) * 128;
        Y = g_H;
    } else {
        X = g_H; xrow0 = yrow0; Y = g_F;
    }

#if HAS_TCGEN05
    const uint32_t sbase = smem_u32(smem);
    const int wid = t >> 5, lane = t & 31;

    if (wid == 0) { TCGEN05_ALLOC(sbase + 0, TMEM_COLS); TCGEN05_RELINQ(); }
    if (t == 0)   { MBARRIER_INIT(sbase + 8, 1); MBARRIER_INIT(sbase + 16, 1); }

    load_split_chunk16(X, W, xrow0, 0, smem, 1024u);
    FENCE_ASYNC_SHARED();
    __syncthreads();

    uint32_t tmem;
    asm volatile("ld.shared.b32 %0, [%1];" : "=r"(tmem) : "r"(sbase + 0));

    int pc0 = 0, pc1 = 0;
#pragma unroll 1
    for (int c = 0; c < NCHUNK; c++) {
        const uint32_t sb = 1024u + (uint32_t)(c & 1) * STAGE_BYTES;
        if (wid == 0 && elect_one_pred()) {
            uint64_t dAhi = MAKE_SMEM_DESC64(sbase + sb + 0u);
            uint64_t dAlo = MAKE_SMEM_DESC64(sbase + sb + 8192u);
            uint64_t dBhi = MAKE_SMEM_DESC64(sbase + sb + 16384u);
            uint64_t dBlo = MAKE_SMEM_DESC64(sbase + sb + 32768u);
#pragma unroll
            for (int ks = 0; ks < 2; ks++)
                mma_tf32_ss(tmem, dAhi + ks * 2, dBhi + ks * 2, (c == 0 && ks == 0) ? 0u : 1u);
#pragma unroll
            for (int ks = 0; ks < 2; ks++)
                mma_tf32_ss(tmem, dAhi + ks * 2, dBlo + ks * 2, 1u);
#pragma unroll
            for (int ks = 0; ks < 2; ks++)
                mma_tf32_ss(tmem, dAlo + ks * 2, dBhi + ks * 2, 1u);
            TCGEN05_COMMIT(sbase + 8 + (uint32_t)(c & 1) * 8u);
        }
        if (c < NCHUNK - 1) {
            int s = (c + 1) & 1;
            if (c >= 1) {      // recycle: wait for chunk c-1 (same stage) to finish
                if (s == 0) { MBARRIER_WAIT_PARITY(sbase + 8,  pc0 & 1); pc0++; }
                else        { MBARRIER_WAIT_PARITY(sbase + 16, pc1 & 1); pc1++; }
            }
            load_split_chunk16(X, W, xrow0, (c + 1) * 16, smem, 1024u + (uint32_t)s * STAGE_BYTES);
            FENCE_ASYNC_SHARED();
            __syncthreads();
        }
    }
    // final chunk (15, odd) committed on mbar1
    MBARRIER_WAIT_PARITY(sbase + 16, pc1 & 1); pc1++;
    TCGEN05_FENCE_AFTER();

    // epilogue: warp w -> rows (w&3)*32+lane, cols (w>>2)*128 .. +127
    {
        const int rsub  = wid & 3;
        const int chalf = (wid >> 2) * 128;
        float* dst = Y + (yrow0 + (size_t)(rsub * 32 + lane)) * DD + chalf;
#pragma unroll
        for (int c0 = 0; c0 < 4; c0++) {
            uint32_t r[32];
            TCGEN05_LD_32X32B_X32(r, tmem + (uint32_t)chalf + (uint32_t)c0 * 32u);
            TCGEN05_WAIT_LD();
#pragma unroll
            for (int j = 0; j < 32; j += 4) {
                float4 v;
                v.x = __uint_as_float(r[j + 0]) + bias[chalf + c0 * 32 + j + 0];
                v.y = __uint_as_float(r[j + 1]) + bias[chalf + c0 * 32 + j + 1];
                v.z = __uint_as_float(r[j + 2]) + bias[chalf + c0 * 32 + j + 2];
                v.w = __uint_as_float(r[j + 3]) + bias[chalf + c0 * 32 + j + 3];
                if (layer == 0) {
                    v.x = fmaxf(v.x, 0.f); v.y = fmaxf(v.y, 0.f);
                    v.z = fmaxf(v.z, 0.f); v.w = fmaxf(v.w, 0.f);
                }
                *(float4*)(dst + c0 * 32 + j) = v;
            }
        }
        TCGEN05_FENCE_BEFORE();
    }
    __syncthreads();
    if (wid == 0) TCGEN05_DEALLOC(tmem, TMEM_COLS);

#else   // ------------------- FFMA fallback (compute_103 pass) -------------
    float* smf = (float*)smem;
    float* Xs = smf;                 // [32][65] k-major
    float* Ws = smf + 32 * 65;       // [32][256] k-major
    const int rg = t >> 4;
    const int cg = t & 15;
    const int lr = t >> 2;
    const int lo = (t & 3) << 3;

#pragma unroll 1
    for (int hrow = 0; hrow < 2; hrow++) {
        const size_t r0 = xrow0 + (size_t)hrow * 64;
        float acc[4][16];
#pragma unroll
        for (int i = 0; i < 4; i++)
#pragma unroll
            for (int j = 0; j < 16; j++) acc[i][j] = 0.f;

        for (int kc = 0; kc < DD; kc += 32) {
            float4 x0 = *(const float4*)(X + (r0 + lr) * DD + kc + lo);
            float4 x1 = *(const float4*)(X + (r0 + lr) * DD + kc + lo + 4);
            float4 wv[8];
#pragma unroll
            for (int j4 = 0; j4 < 8; j4++)
                wv[j4] = *(const float4*)(W + (size_t)t * DD + kc + j4 * 4);
            __syncthreads();
            Xs[(lo+0)*65+lr]=x0.x; Xs[(lo+1)*65+lr]=x0.y; Xs[(lo+2)*65+lr]=x0.z; Xs[(lo+3)*65+lr]=x0.w;
            Xs[(lo+4)*65+lr]=x1.x; Xs[(lo+5)*65+lr]=x1.y; Xs[(lo+6)*65+lr]=x1.z; Xs[(lo+7)*65+lr]=x1.w;
#pragma unroll
            for (int j4 = 0; j4 < 8; j4++) {
                Ws[(j4*4+0)*256+t]=wv[j4].x; Ws[(j4*4+1)*256+t]=wv[j4].y;
                Ws[(j4*4+2)*256+t]=wv[j4].z; Ws[(j4*4+3)*256+t]=wv[j4].w;
            }
            __syncthreads();
#pragma unroll
            for (int dk = 0; dk < 32; dk++) {
                float a[4], bv[16];
#pragma unroll
                for (int i = 0; i < 4; i++) a[i] = Xs[dk*65 + rg + 16*i];
#pragma unroll
                for (int j = 0; j < 16; j++) bv[j] = Ws[dk*256 + cg + 16*j];
#pragma unroll
                for (int i = 0; i < 4; i++)
#pragma unroll
                    for (int j = 0; j < 16; j++) acc[i][j] = fmaf(a[i], bv[j], acc[i][j]);
            }
        }
        __syncthreads();
#pragma unroll
        for (int j = 0; j < 16; j++) {
            float bj = bias[cg + 16*j];
#pragma unroll
            for (int i = 0; i < 4; i++) {
                float v = acc[i][j] + bj;
                if (layer == 0) v = fmaxf(v, 0.f);
                Y[(yrow0 + (size_t)hrow*64 + rg + 16*i) * DD + cg + 16*j] = v;
            }
        }
    }
#endif
}

// ---------------------------------------------------------------------------
// Kernel 2: per-batch cdist + Sinkhorn + power iters, fully in SMEM. (unchanged)
// ---------------------------------------------------------------------------
#define SMEM2_FLOATS (64*33*2 + 64*65*3 + 8*64 + 8)

__global__ __launch_bounds__(256, 3)
void sinkhorn_kernel(const float* __restrict__ mq, const float* __restrict__ mr,
                     float* __restrict__ out)
{
    extern __shared__ float sm[];
    float* Qs   = sm;
    float* Rs   = Qs + 64*33;
    float* Cs   = Rs + 64*33;
    float* lKs  = Cs + 64*65;
    float* Ts   = lKs + 64*65;
    float* nqs  = Ts + 64*65;
    float* nrs  = nqs + 64;
    float* lmqs = nrs + 64;
    float* lmrs = lmqs + 64;
    float* las  = lmrs + 64;
    float* lbs  = las + 64;
    float* rss  = lbs + 64;
    float* css  = rss + 64;
    float* wred = css + 64;

    const int t = threadIdx.x;
    const int w = t >> 5, lane = t & 31;
    const int tr = t >> 4, tc = t & 15;
    const int lr = t >> 2, lo = (t & 3) << 3;
    const int r4 = t >> 2;
    const int q4 = (t & 3) * 16;
    const int b = blockIdx.x;

    const float* Fq = g_F;
    const float* Fr = g_F + HALF_OFF;

    if (t < 64) {
        nqs[t] = 0.f; nrs[t] = 0.f;
        lmqs[t] = __logf(fmaxf(mq[b*64 + t], 1e-8f));
        lmrs[t] = __logf(fmaxf(mr[b*64 + t], 1e-8f));
        las[t] = 0.f; lbs[t] = 0.f;
    }

    float g[4][4];
#pragma unroll
    for (int i = 0; i < 4; i++)
#pragma unroll
        for (int j = 0; j < 4; j++) g[i][j] = 0.f;

    for (int kc = 0; kc < DD; kc += 32) {
        float4 q0 = *(const float4*)(Fq + ((size_t)b*64 + lr)*DD + kc + lo);
        float4 q1 = *(const float4*)(Fq + ((size_t)b*64 + lr)*DD + kc + lo + 4);
        float4 r0 = *(const float4*)(Fr + ((size_t)b*64 + lr)*DD + kc + lo);
        float4 r1 = *(const float4*)(Fr + ((size_t)b*64 + lr)*DD + kc + lo + 4);
        __syncthreads();
        Qs[lr*33+lo+0]=q0.x; Qs[lr*33+lo+1]=q0.y; Qs[lr*33+lo+2]=q0.z; Qs[lr*33+lo+3]=q0.w;
        Qs[lr*33+lo+4]=q1.x; Qs[lr*33+lo+5]=q1.y; Qs[lr*33+lo+6]=q1.z; Qs[lr*33+lo+7]=q1.w;
        Rs[lr*33+lo+0]=r0.x; Rs[lr*33+lo+1]=r0.y; Rs[lr*33+lo+2]=r0.z; Rs[lr*33+lo+3]=r0.w;
        Rs[lr*33+lo+4]=r1.x; Rs[lr*33+lo+5]=r1.y; Rs[lr*33+lo+6]=r1.z; Rs[lr*33+lo+7]=r1.w;
        __syncthreads();
        {
            float vq = 0.f, vr = 0.f;
            int k0 = (t & 3) * 8;
#pragma unroll
            for (int j = 0; j < 8; j++) {
                float a = Qs[r4*33 + k0 + j]; vq = fmaf(a, a, vq);
                float c = Rs[r4*33 + k0 + j]; vr = fmaf(c, c, vr);
            }
            vq += __shfl_xor_sync(0xffffffffu, vq, 1);
            vq += __shfl_xor_sync(0xffffffffu, vq, 2);
            vr += __shfl_xor_sync(0xffffffffu, vr, 1);
            vr += __shfl_xor_sync(0xffffffffu, vr, 2);
            if ((t & 3) == 0) { nqs[r4] += vq; nrs[r4] += vr; }
        }
#pragma unroll
        for (int dk = 0; dk < 32; dk++) {
            float a[4], bv[4];
#pragma unroll
            for (int i = 0; i < 4; i++) a[i]  = Qs[(16*i + tr)*33 + dk];
#pragma unroll
            for (int j = 0; j < 4; j++) bv[j] = Rs[(16*j + tc)*33 + dk];
#pragma unroll
            for (int i = 0; i < 4; i++)
#pragma unroll
                for (int j = 0; j < 4; j++) g[i][j] = fmaf(a[i], bv[j], g[i][j]);
        }
    }
    __syncthreads();

#pragma unroll
    for (int i = 0; i < 4; i++) {
        int k = 16*i + tr;
#pragma unroll
        for (int j = 0; j < 4; j++) {
            int m = 16*j + tc;
            float v  = nqs[k] + nrs[m] - 2.f*g[i][j];
            float Cv = sqrtf(fmaxf(v, 0.f));
            Cs[k*65 + m]  = Cv;
            lKs[k*65 + m] = fmaf(-INV_EPS, Cv, lmqs[k] + lmrs[m]);
        }
    }
    __syncthreads();

    for (int it = 0; it < NITR; it++) {
        {
            float vb[16];
            float mx = -1e30f;
#pragma unroll
            for (int j = 0; j < 16; j++) {
                vb[j] = lKs[r4*65 + q4 + j] + lbs[q4 + j];
                mx = fmaxf(mx, vb[j]);
            }
            mx = fmaxf(mx, __shfl_xor_sync(0xffffffffu, mx, 1));
            mx = fmaxf(mx, __shfl_xor_sync(0xffffffffu, mx, 2));
            float ss = 0.f;
#pragma unroll
            for (int j = 0; j < 16; j++) ss += __expf(vb[j] - mx);
            ss += __shfl_xor_sync(0xffffffffu, ss, 1);
            ss += __shfl_xor_sync(0xffffffffu, ss, 2);
            if ((t & 3) == 0) las[r4] = -(mx + __logf(ss));
        }
        __syncthreads();
        {
            float vb[16];
            float mx = -1e30f;
#pragma unroll
            for (int j = 0; j < 16; j++) {
                vb[j] = lKs[(q4 + j)*65 + r4] + las[q4 + j];
                mx = fmaxf(mx, vb[j]);
            }
            mx = fmaxf(mx, __shfl_xor_sync(0xffffffffu, mx, 1));
            mx = fmaxf(mx, __shfl_xor_sync(0xffffffffu, mx, 2));
            float ss = 0.f;
#pragma unroll
            for (int j = 0; j < 16; j++) ss += __expf(vb[j] - mx);
            ss += __shfl_xor_sync(0xffffffffu, ss, 1);
            ss += __shfl_xor_sync(0xffffffffu, ss, 2);
            if ((t & 3) == 0) lbs[r4] = -(mx + __logf(ss));
        }
        __syncthreads();
    }

    for (int idx = t; idx < 4096; idx += 256) {
        int k = idx >> 6, m = idx & 63;
        Ts[k*65 + m] = __expf(lKs[k*65 + m] + las[k] + lbs[m]);
    }
    __syncthreads();

    for (int p = 0; p < MITR; p++) {
        {
            float ssum = 0.f;
#pragma unroll
            for (int j = 0; j < 16; j++) {
                float v = Ts[r4*65 + q4 + j];
                v *= v;
                Ts[r4*65 + q4 + j] = v;
                ssum += v;
            }
            ssum += __shfl_xor_sync(0xffffffffu, ssum, 1);
            ssum += __shfl_xor_sync(0xffffffffu, ssum, 2);
            if ((t & 3) == 0) rss[r4] = ssum + 1e-8f;
        }
        __syncthreads();
        {
            float ssum = 0.f;
#pragma unroll
            for (int j = 0; j < 16; j++) {
                float v = Ts[(q4 + j)*65 + r4] / rss[q4 + j];
                Ts[(q4 + j)*65 + r4] = v;
                ssum += v;
            }
            ssum += __shfl_xor_sync(0xffffffffu, ssum, 1);
            ssum += __shfl_xor_sync(0xffffffffu, ssum, 2);
            if ((t & 3) == 0) css[r4] = ssum + 1e-8f;
        }
        __syncthreads();
        {
#pragma unroll
            for (int j = 0; j < 16; j++)
                Ts[r4*65 + q4 + j] /= css[q4 + j];
        }
        __syncthreads();
    }

    size_t tbase = OUT_T + (size_t)b*4096;
    size_t cbase = OUT_C + (size_t)b*4096;
    float part = 0.f;
    for (int idx = t; idx < 4096; idx += 256) {
        int k = idx >> 6, m = idx & 63;
        float tv = Ts[k*65 + m];
        float cv = Cs[k*65 + m];
        out[tbase + idx] = tv;
        out[cbase + idx] = cv;
        part += tv * cv;
    }
    part = wredsum(part);
    if (lane == 0) wred[w] = part;
    __syncthreads();
    if (t == 0) {
        float cv = 0.f;
#pragma unroll
        for (int i = 0; i < 8; i++) cv += wred[i];
        out[b] = 1.f / (1.f + expf(cv));
        out[OUT_CV + b] = cv;
    }
}

// ---------------------------------------------------------------------------
extern "C" void kernel_launch(void* const* d_in, const int* in_sizes, int n_in,
                              void* d_out, int out_size)
{
    const float* sq = (const float*)d_in[0];
    const float* sr = (const float*)d_in[1];
    const float* mq = (const float*)d_in[2];
    const float* mr = (const float*)d_in[3];
    const float* W1 = (const float*)d_in[4];
    const float* b1 = (const float*)d_in[5];
    const float* W2 = (const float*)d_in[6];
    const float* b2 = (const float*)d_in[7];
    float* out = (float*)d_out;

    const int smem2 = SMEM2_FLOATS * 4;
    cudaFuncSetAttribute(mma_mlp_layer,   cudaFuncAttributeMaxDynamicSharedMemorySize, SMEM_MMA);
    cudaFuncSetAttribute(sinkhorn_kernel, cudaFuncAttributeMaxDynamicSharedMemorySize, smem2);

    mma_mlp_layer<<<2048, 256, SMEM_MMA>>>(sq, sr, W1, b1, 0);
    mma_mlp_layer<<<2048, 256, SMEM_MMA>>>(sq, sr, W2, b2, 1);
    sinkhorn_kernel<<<BB, 256, smem2>>>(mq, mr, out);
}